// round 9
// baseline (speedup 1.0000x reference)
#include <cuda_runtime.h>

// embedding_pooling: out[b, (c-1)*256 + d] = relu(max_{l: label[b,l]==c} x[b,l,d]), empty->0
//  - relu + empty-case == fmax chain initialized at 0.
//  - Labels are int32 on device (proven R2 fail / R3 pass).
//
// Persistent work-stealing: grid = 1184 CTAs x 256 threads (= full chip, one
// wave at 8 CTAs/SM), tiles = 1280 (b,class) pairs pulled from a global atomic
// counter. Early finishers absorb the surplus tiles and duration variance,
// removing the end-of-kernel BW droop that capped DRAM at ~63%.
// Per tile: ballot-ordered gather of matching l's, then warp-strided
// 2 x LDG.128 + 8 FMNMX streaming max.

#define BATCH 256
#define LSEQ  512
#define DDIM  256
#define NC    5
#define NTILES (BATCH * NC)
#define GRID   1184

__device__ unsigned g_tile_ctr;

__global__ void reset_ctr_kernel() { g_tile_ctr = 0u; }

__global__ __launch_bounds__(256, 8)
void embedding_pooling_kernel(const float* __restrict__ x,
                              const int* __restrict__ labels,
                              float* __restrict__ out)
{
    __shared__ int      s_idx[LSEQ];
    __shared__ int      s_base[17];
    __shared__ float4   s_red[8][64];
    __shared__ unsigned s_tile;

    const int tid  = threadIdx.x;
    const int w    = tid >> 5;
    const int lane = tid & 31;
    const unsigned below = (1u << lane) - 1u;
    const float4* X4 = (const float4*)x;

    for (;;) {
        if (tid == 0) s_tile = atomicAdd(&g_tile_ctr, 1u);
        __syncthreads();                       // publishes s_tile; guards smem reuse
        const unsigned tile = s_tile;
        if (tile >= NTILES) return;

        const int b = tile / NC;
        const int c = (tile % NC) + 1;

        // ---- Phase 1: ordered compaction of l with label == c.
        const int* lab_row = labels + (size_t)b * LSEQ;
        const int l0 = tid, l1 = tid + 256;
        const bool f0 = (lab_row[l0] == c);
        const bool f1 = (lab_row[l1] == c);
        const unsigned m0 = __ballot_sync(0xffffffffu, f0);
        const unsigned m1 = __ballot_sync(0xffffffffu, f1);
        if (lane == 0) {
            s_base[w]     = __popc(m0);
            s_base[8 + w] = __popc(m1);
        }
        __syncthreads();
        if (tid == 0) {
            int acc = 0;
#pragma unroll
            for (int i = 0; i < 16; i++) {
                const int t = s_base[i];
                s_base[i] = acc;
                acc += t;
            }
            s_base[16] = acc;
        }
        __syncthreads();
        if (f0) s_idx[s_base[w]     + __popc(m0 & below)] = l0;
        if (f1) s_idx[s_base[8 + w] + __popc(m1 & below)] = l1;
        __syncthreads();
        const int n = s_base[16];

        // ---- Phase 2: warp-strided max over gathered rows.
        const int base_row = b * LSEQ;
        float4 m0v = make_float4(0.f, 0.f, 0.f, 0.f);
        float4 m1v = make_float4(0.f, 0.f, 0.f, 0.f);

#pragma unroll 2
        for (int j = w; j < n; j += 8) {
            const int l = s_idx[j];
            const float4* row = X4 + (size_t)(base_row + l) * (DDIM / 4);
            const float4 v0 = row[lane];
            const float4 v1 = row[32 + lane];
            m0v.x = fmaxf(m0v.x, v0.x); m0v.y = fmaxf(m0v.y, v0.y);
            m0v.z = fmaxf(m0v.z, v0.z); m0v.w = fmaxf(m0v.w, v0.w);
            m1v.x = fmaxf(m1v.x, v1.x); m1v.y = fmaxf(m1v.y, v1.y);
            m1v.z = fmaxf(m1v.z, v1.z); m1v.w = fmaxf(m1v.w, v1.w);
        }

        s_red[w][lane]      = m0v;
        s_red[w][32 + lane] = m1v;
        __syncthreads();

        // ---- Phase 3: fold 8 warps; one float4 store per column.
        if (tid < 64) {
            float4 mm = s_red[0][tid];
#pragma unroll
            for (int g = 1; g < 8; g++) {
                const float4 v = s_red[g][tid];
                mm.x = fmaxf(mm.x, v.x); mm.y = fmaxf(mm.y, v.y);
                mm.z = fmaxf(mm.z, v.z); mm.w = fmaxf(mm.w, v.w);
            }
            float4* O4 = (float4*)out;
            O4[(size_t)b * (NC * (DDIM / 4)) + (size_t)(c - 1) * (DDIM / 4) + tid] = mm;
        }
        // loop-top __syncthreads() protects s_idx/s_base/s_red for next tile
    }
}

extern "C" void kernel_launch(void* const* d_in, const int* in_sizes, int n_in,
                              void* d_out, int out_size)
{
    const float* x      = (const float*)d_in[0];
    const int*   labels = (const int*)d_in[1];
    float*       out    = (float*)d_out;

    reset_ctr_kernel<<<1, 1>>>();
    embedding_pooling_kernel<<<GRID, 256>>>(x, labels, out);
}